// round 5
// baseline (speedup 1.0000x reference)
#include <cuda_runtime.h>

#define IN_H   1024
#define IN_W   1024
#define OUT_H  256
#define OUT_W  256
#define NTAP   16

#define VCHUNK 8                    // output rows per block strip
#define HROWS  4                    // output rows per V-half
#define HVROWS (4*HROWS + 12)       // 28 input rows per half

// ---------------------------------------------------------------------------
// Fused separable bicubic 4x downsample, register-lean for 6 CTAs/SM.
// Block = (img, 8 output rows) strip, 256 threads, 32 KB smem.
// Phase V runs as TWO halves of 4 output rows (4 float4 accs = 16 regs),
// halves overlap by 12 input rows (same-thread re-reads -> L1 hits).
// Phase H: 16-tap from smem via 5 conflict-free LDS.128.
// ---------------------------------------------------------------------------
__global__ __launch_bounds__(256, 6)
void bicubic_fused(const float* __restrict__ in, float* __restrict__ out)
{
    constexpr float W[NTAP] = {
        -0.001708984375f, -0.010986328125f, -0.018310546875f, -0.011962890625f,
         0.022705078125f,  0.097412109375f,  0.181884765625f,  0.240966796875f,
         0.240966796875f,  0.181884765625f,  0.097412109375f,  0.022705078125f,
        -0.011962890625f, -0.018310546875f, -0.010986328125f, -0.001708984375f };

    __shared__ __align__(16) float s[VCHUNK][IN_W];   // 32 KB

    const int tid = threadIdx.x;                 // float4-column 0..255
    const int o0  = blockIdx.x * VCHUNK;         // first output row
    const int img = blockIdx.y;

    const float4* __restrict__ inp =
        (const float4*)(in + (size_t)img * (IN_H * IN_W));

    // ---- Phase V: two halves of 4 output rows each ----
#pragma unroll
    for (int h = 0; h < 2; ++h) {
        const int Rh = 4 * o0 - 6 + 16 * h;      // first input row of this half

        float4 acc[HROWS];
#pragma unroll
        for (int j = 0; j < HROWS; ++j) acc[j] = make_float4(0.f, 0.f, 0.f, 0.f);

#pragma unroll
        for (int i = 0; i < HVROWS; ++i) {
            const int gr = min(max(Rh + i, 0), IN_H - 1);
            const float4 v = __ldg(inp + (size_t)gr * (IN_W / 4) + tid);
#pragma unroll
            for (int j = 0; j < HROWS; ++j) {
                const int k = i - 4 * j;         // tap index (compile-time pruned)
                if (k >= 0 && k < NTAP) {
                    acc[j].x = fmaf(W[k], v.x, acc[j].x);
                    acc[j].y = fmaf(W[k], v.y, acc[j].y);
                    acc[j].z = fmaf(W[k], v.z, acc[j].z);
                    acc[j].w = fmaf(W[k], v.w, acc[j].w);
                }
            }
        }

#pragma unroll
        for (int j = 0; j < HROWS; ++j)
            ((float4*)s[4 * h + j])[tid] = acc[j];
    }
    __syncthreads();

    // ---- Phase H: horizontal 16-tap, one output column per thread ----
    const int oc = tid;
    float* __restrict__ outp = out + ((size_t)img * OUT_H + o0) * OUT_W + oc;

#pragma unroll
    for (int j = 0; j < VCHUNK; ++j) {
        const float* __restrict__ srow = s[j];
        float r;
        if (oc >= 2 && oc <= 253) {
            const float4* __restrict__ sv = (const float4*)srow;
            const float4 a = sv[oc - 2];
            const float4 b = sv[oc - 1];
            const float4 c = sv[oc];
            const float4 d = sv[oc + 1];
            const float4 e = sv[oc + 2];
            r = W[0] * a.z;                      // tap 0 = s[4oc-6]
            r = fmaf(W[1],  a.w, r);
            r = fmaf(W[2],  b.x, r);
            r = fmaf(W[3],  b.y, r);
            r = fmaf(W[4],  b.z, r);
            r = fmaf(W[5],  b.w, r);
            r = fmaf(W[6],  c.x, r);
            r = fmaf(W[7],  c.y, r);
            r = fmaf(W[8],  c.z, r);
            r = fmaf(W[9],  c.w, r);
            r = fmaf(W[10], d.x, r);
            r = fmaf(W[11], d.y, r);
            r = fmaf(W[12], d.z, r);
            r = fmaf(W[13], d.w, r);
            r = fmaf(W[14], e.x, r);
            r = fmaf(W[15], e.y, r);             // tap 15 = s[4oc+9]
        } else {
            r = 0.f;
#pragma unroll
            for (int k = 0; k < NTAP; ++k)
                r = fmaf(W[k], srow[min(max(4 * oc - 6 + k, 0), IN_W - 1)], r);
        }
        outp[(size_t)j * OUT_W] = r;
    }
}

extern "C" void kernel_launch(void* const* d_in, const int* in_sizes, int n_in,
                              void* d_out, int out_size)
{
    const float* in  = (const float*)d_in[0];
    float*       out = (float*)d_out;

    const int nimg = in_sizes[0] / (IN_H * IN_W);       // 24

    dim3 grid(OUT_H / VCHUNK, nimg);                    // 32 x 24 = 768 blocks
    bicubic_fused<<<grid, 256>>>(in, out);
}

// round 6
// speedup vs baseline: 1.0942x; 1.0942x over previous
#include <cuda_runtime.h>

#define IN_H   1024
#define IN_W   1024
#define OUT_H  256
#define OUT_W  256
#define NTAP   16

#define VCHUNK 8                    // output rows per strip
#define VROWS  (4*VCHUNK + 12)      // 44 input rows feed 8 output rows
#define STRIPS_PER_BLOCK 2
#define XBLKS  (OUT_H / VCHUNK / STRIPS_PER_BLOCK)   // 16

// ---------------------------------------------------------------------------
// Fused separable bicubic 4x downsample (R4 structure, single balanced wave).
// Grid = 16 x 24 = 384 blocks (fits one wave @ 4 CTAs/SM); each block does
// 2 strips: blockIdx.x and blockIdx.x+16 (concurrent strips stay adjacent,
// preserving L2 halo dedup).
// ---------------------------------------------------------------------------
__global__ __launch_bounds__(256)
void bicubic_fused(const float* __restrict__ in, float* __restrict__ out)
{
    constexpr float W[NTAP] = {
        -0.001708984375f, -0.010986328125f, -0.018310546875f, -0.011962890625f,
         0.022705078125f,  0.097412109375f,  0.181884765625f,  0.240966796875f,
         0.240966796875f,  0.181884765625f,  0.097412109375f,  0.022705078125f,
        -0.011962890625f, -0.018310546875f, -0.010986328125f, -0.001708984375f };

    __shared__ __align__(16) float s[VCHUNK][IN_W];   // 32 KB

    const int tid = threadIdx.x;                 // float4-column 0..255
    const int img = blockIdx.y;

    const float4* __restrict__ inp =
        (const float4*)(in + (size_t)img * (IN_H * IN_W));

#pragma unroll 1
    for (int it = 0; it < STRIPS_PER_BLOCK; ++it) {
        const int strip = blockIdx.x + XBLKS * it;   // 0..31
        const int o0    = strip * VCHUNK;
        const int R0    = 4 * o0 - 6;

        // ---- Phase V: vertical 16-tap into registers ----
        float4 acc[VCHUNK];
#pragma unroll
        for (int j = 0; j < VCHUNK; ++j) acc[j] = make_float4(0.f, 0.f, 0.f, 0.f);

#pragma unroll
        for (int i = 0; i < VROWS; ++i) {
            const int gr = min(max(R0 + i, 0), IN_H - 1);
            const float4 v = __ldg(inp + (size_t)gr * (IN_W / 4) + tid);
#pragma unroll
            for (int j = 0; j < VCHUNK; ++j) {
                const int k = i - 4 * j;         // tap index (compile-time pruned)
                if (k >= 0 && k < NTAP) {
                    acc[j].x = fmaf(W[k], v.x, acc[j].x);
                    acc[j].y = fmaf(W[k], v.y, acc[j].y);
                    acc[j].z = fmaf(W[k], v.z, acc[j].z);
                    acc[j].w = fmaf(W[k], v.w, acc[j].w);
                }
            }
        }

        // ---- dump strip to smem: STS.128, conflict-free ----
#pragma unroll
        for (int j = 0; j < VCHUNK; ++j)
            ((float4*)s[j])[tid] = acc[j];
        __syncthreads();

        // ---- Phase H: horizontal 16-tap, one output column per thread ----
        const int oc = tid;
        float* __restrict__ outp =
            out + ((size_t)img * OUT_H + o0) * OUT_W + oc;

#pragma unroll
        for (int j = 0; j < VCHUNK; ++j) {
            const float* __restrict__ srow = s[j];
            float r;
            if (oc >= 2 && oc <= 253) {
                const float4* __restrict__ sv = (const float4*)srow;
                const float4 a = sv[oc - 2];
                const float4 b = sv[oc - 1];
                const float4 c = sv[oc];
                const float4 d = sv[oc + 1];
                const float4 e = sv[oc + 2];
                r = W[0] * a.z;                  // tap 0 = s[4oc-6]
                r = fmaf(W[1],  a.w, r);
                r = fmaf(W[2],  b.x, r);
                r = fmaf(W[3],  b.y, r);
                r = fmaf(W[4],  b.z, r);
                r = fmaf(W[5],  b.w, r);
                r = fmaf(W[6],  c.x, r);
                r = fmaf(W[7],  c.y, r);
                r = fmaf(W[8],  c.z, r);
                r = fmaf(W[9],  c.w, r);
                r = fmaf(W[10], d.x, r);
                r = fmaf(W[11], d.y, r);
                r = fmaf(W[12], d.z, r);
                r = fmaf(W[13], d.w, r);
                r = fmaf(W[14], e.x, r);
                r = fmaf(W[15], e.y, r);         // tap 15 = s[4oc+9]
            } else {
                r = 0.f;
#pragma unroll
                for (int k = 0; k < NTAP; ++k)
                    r = fmaf(W[k], srow[min(max(4 * oc - 6 + k, 0), IN_W - 1)], r);
            }
            outp[(size_t)j * OUT_W] = r;
        }
        __syncthreads();    // smem reused by next strip's V dump
    }
}

extern "C" void kernel_launch(void* const* d_in, const int* in_sizes, int n_in,
                              void* d_out, int out_size)
{
    const float* in  = (const float*)d_in[0];
    float*       out = (float*)d_out;

    const int nimg = in_sizes[0] / (IN_H * IN_W);       // 24

    dim3 grid(XBLKS, nimg);                             // 16 x 24 = 384 blocks
    bicubic_fused<<<grid, 256>>>(in, out);
}